// round 2
// baseline (speedup 1.0000x reference)
#include <cuda_runtime.h>
#include <math.h>
#include <stdint.h>

#define NN 100000
#define EE 1250000
#define TT 8

// ---------------- device scratch (static, no allocation) ----------------
__device__ __align__(128) int   g_deg[NN];
__device__ __align__(128) int   g_cnt[NN];
__device__ __align__(128) int   g_cursor[NN];
__device__ __align__(128) int   g_rowptr[NN + 1];
__device__ __align__(128) int   g_bsum[256];
__device__ __align__(128) int   g_boff[256];
__device__ __align__(128) float g_dinv[NN];
__device__ __align__(128) int   g_col[EE];
__device__ __align__(128) float g_w[EE];
__device__ int g_is64;

__device__ __align__(128) float g_h[(size_t)NN * 64];
__device__ __align__(128) float g_mvx[(size_t)NN * 64];
__device__ __align__(128) float g_mvh[(size_t)NN * 64];
__device__ __align__(128) float g_hr[(size_t)NN * 64];
__device__ __align__(128) float g_mvhr[(size_t)NN * 64];
__device__ __align__(128) float g_z[(size_t)NN * 64];

__device__ __align__(128) float g_Wzr[256 * 128];
__device__ __align__(128) float g_Wh[256 * 64];
__device__ __align__(128) float g_bz[64];
__device__ __align__(128) float g_br[64];
__device__ __align__(128) float g_bh[64];

// ---------------- dtype detection for edge_index (int32 vs int64) ----------
// int64 indices < 2^31 -> every odd int32 word is 0. With int32 data the odd
// words are independent indices in [0, N); 512 consecutive zeros ~ impossible.
__global__ void k_detect(const int* __restrict__ ei) {
    if (blockIdx.x == 0 && threadIdx.x == 0) {
        int is64 = 1;
        for (int i = 0; i < 512; i++)
            if (ei[2 * i + 1] != 0) { is64 = 0; break; }
        g_is64 = is64;
    }
}

__device__ __forceinline__ int load_idx(const void* ei, size_t i) {
    if (g_is64) return (int)((const long long*)ei)[i];
    return ((const int*)ei)[i];
}

// ---------------- setup kernels ----------------
__global__ void k_zero_setup(int n) {
    int i = blockIdx.x * blockDim.x + threadIdx.x;
    if (i < n) { g_deg[i] = 0; g_cnt[i] = 0; g_cursor[i] = 0; }
}

__global__ void k_zero_h() {
    int i = blockIdx.x * blockDim.x + threadIdx.x;
    if (i < NN * 64) g_h[i] = 0.0f;
}

__global__ void k_hist(const void* __restrict__ ei, int E) {
    int e = blockIdx.x * blockDim.x + threadIdx.x;
    if (e < E) {
        int s = load_idx(ei, e);
        int d = load_idx(ei, (size_t)E + e);
        if (s >= 0 && s < NN) atomicAdd(&g_deg[s], 1);
        if (d >= 0 && d < NN) atomicAdd(&g_cnt[d], 1);
    }
}

__global__ void k_dinv(int n) {
    int i = blockIdx.x * blockDim.x + threadIdx.x;
    if (i < n) {
        int d = g_deg[i];
        g_dinv[i] = (d > 0) ? rsqrtf((float)d) : 0.0f;
    }
}

__global__ void k_scan1(int n) {
    __shared__ int s[1024];
    int tid = threadIdx.x;
    int gid = blockIdx.x * 1024 + tid;
    int v = (gid < n) ? g_cnt[gid] : 0;
    s[tid] = v;
    __syncthreads();
    #pragma unroll
    for (int off = 1; off < 1024; off <<= 1) {
        int t = (tid >= off) ? s[tid - off] : 0;
        __syncthreads();
        s[tid] += t;
        __syncthreads();
    }
    if (gid < n) g_rowptr[gid] = s[tid] - v;   // exclusive
    if (tid == 1023) g_bsum[blockIdx.x] = s[1023];
}

__global__ void k_scan2(int nb) {
    if (threadIdx.x == 0) {
        int acc = 0;
        for (int i = 0; i < nb; i++) { int t = g_bsum[i]; g_boff[i] = acc; acc += t; }
    }
}

__global__ void k_scan3(int n, int E) {
    int gid = blockIdx.x * blockDim.x + threadIdx.x;
    if (gid < n) g_rowptr[gid] += g_boff[gid >> 10];
    if (gid == 0) g_rowptr[n] = E;
}

__global__ void k_fill(const void* __restrict__ ei, int E) {
    int e = blockIdx.x * blockDim.x + threadIdx.x;
    if (e >= E) return;
    int s = load_idx(ei, e);
    int d = load_idx(ei, (size_t)E + e);
    if (s < 0 || s >= NN || d < 0 || d >= NN) return;
    int pos = g_rowptr[d] + atomicAdd(&g_cursor[d], 1);
    g_col[pos] = s;
    g_w[pos] = -g_dinv[s] * g_dinv[d];
}

// pack fused weight matrices + biases
__global__ void k_pack(const float* __restrict__ Wxz, const float* __restrict__ Whz,
                       const float* __restrict__ Wxr, const float* __restrict__ Whr,
                       const float* __restrict__ Wxh, const float* __restrict__ Whh,
                       const float* __restrict__ bxz, const float* __restrict__ bhz,
                       const float* __restrict__ bxr, const float* __restrict__ bhr,
                       const float* __restrict__ bxh, const float* __restrict__ bhh) {
    int i = blockIdx.x * blockDim.x + threadIdx.x;
    if (i < 256 * 128) {
        int k = i >> 7, c = i & 127;
        int kb = k >> 6, kr = k & 63;
        const float* Wx; const float* Wh_; int cc;
        if (c < 64) { Wx = Wxz; Wh_ = Whz; cc = c; }
        else        { Wx = Wxr; Wh_ = Whr; cc = c - 64; }
        float v = (kb < 2) ? Wx[kb * 4096 + kr * 64 + cc]
                           : Wh_[(kb - 2) * 4096 + kr * 64 + cc];
        g_Wzr[i] = v;
    } else if (i < 256 * 128 + 256 * 64) {
        int j = i - 256 * 128;
        int k = j >> 6, c = j & 63;
        int kb = k >> 6, kr = k & 63;
        float v = (kb < 2) ? Wxh[kb * 4096 + kr * 64 + c]
                           : Whh[(kb - 2) * 4096 + kr * 64 + c];
        g_Wh[j] = v;
    } else if (i < 256 * 128 + 256 * 64 + 192) {
        int c = i - (256 * 128 + 256 * 64);
        if (c < 64)       g_bz[c]       = bxz[c] + bhz[c];
        else if (c < 128) g_br[c - 64]  = bxr[c - 64] + bhr[c - 64];
        else              g_bh[c - 128] = bxh[c - 128] + bhh[c - 128];
    }
}

// ---------------- spmv: y = L_tilde @ x (CSR by dst) ----------------
__global__ void k_spmv(const float* __restrict__ x, float* __restrict__ y, int n) {
    int row = blockIdx.x * 4 + threadIdx.y;
    if (row >= n) return;
    int f = threadIdx.x;               // 0..63
    int s = g_rowptr[row], e = g_rowptr[row + 1];
    float acc = 0.0f;
    for (int p = s; p < e; p++) {
        int c = g_col[p];
        float w = g_w[p];
        acc += w * x[(size_t)c * 64 + f];
    }
    y[(size_t)row * 64 + f] = acc;
}

// ---------------- fused GEMM mainloop: [A0|A1|A2|A3](Nx256) @ W(256xBN) ----------------
template <int BN, int THREADS>
__device__ __forceinline__ void gemm_main(
    const float* __restrict__ A0, const float* __restrict__ A1,
    const float* __restrict__ A2, const float* __restrict__ A3,
    const float* __restrict__ W, int n,
    float (&acc)[8][8], float (&As)[32][132], float (&Ws)[32][BN])
{
    const int tid = threadIdx.x;
    const int rowBase = blockIdx.x * 128;
    const int tx = tid % (BN / 8);
    const int ty = tid / (BN / 8);

    #pragma unroll
    for (int kt = 0; kt < 8; kt++) {
        const float* Ab = (kt < 2) ? A0 : (kt < 4) ? A1 : (kt < 6) ? A2 : A3;
        const int kcol = (kt & 1) * 32;

        // load A tile (128 rows x 32 k), transposed into shared
        #pragma unroll
        for (int i = 0; i < 1024 / THREADS; i++) {
            int idx = tid + i * THREADS;        // float4 index
            int r = idx >> 3, c4 = idx & 7;
            int gr = rowBase + r;
            float4 v = make_float4(0.f, 0.f, 0.f, 0.f);
            if (gr < n)
                v = *reinterpret_cast<const float4*>(Ab + (size_t)gr * 64 + kcol + c4 * 4);
            As[c4 * 4 + 0][r] = v.x;
            As[c4 * 4 + 1][r] = v.y;
            As[c4 * 4 + 2][r] = v.z;
            As[c4 * 4 + 3][r] = v.w;
        }
        // load W tile (32 x BN)
        #pragma unroll
        for (int i = 0; i < (32 * BN / 4) / THREADS; i++) {
            int idx = tid + i * THREADS;        // float4 index
            int r = idx / (BN / 4), c4 = idx % (BN / 4);
            *reinterpret_cast<float4*>(&Ws[r][c4 * 4]) =
                *reinterpret_cast<const float4*>(W + (size_t)(kt * 32 + r) * BN + c4 * 4);
        }
        __syncthreads();

        #pragma unroll
        for (int kk = 0; kk < 32; kk++) {
            float a[8], b[8];
            *reinterpret_cast<float4*>(a)     = *reinterpret_cast<const float4*>(&As[kk][ty * 8]);
            *reinterpret_cast<float4*>(a + 4) = *reinterpret_cast<const float4*>(&As[kk][ty * 8 + 4]);
            *reinterpret_cast<float4*>(b)     = *reinterpret_cast<const float4*>(&Ws[kk][tx * 8]);
            *reinterpret_cast<float4*>(b + 4) = *reinterpret_cast<const float4*>(&Ws[kk][tx * 8 + 4]);
            #pragma unroll
            for (int ii = 0; ii < 8; ii++)
                #pragma unroll
                for (int jj = 0; jj < 8; jj++)
                    acc[ii][jj] += a[ii] * b[jj];
        }
        __syncthreads();
    }
}

__device__ __forceinline__ float sigmoidf_(float x) { return 1.0f / (1.0f + expf(-x)); }

// z/r GEMM: A = [x_t | mvx | h | mvh], W = g_Wzr (256x128)
// epilogue: cols 0..63 -> z = sigmoid(.); cols 64..127 -> hr = h * sigmoid(.)
__global__ __launch_bounds__(256)
void k_gemm_zr(const float* __restrict__ xt, const float* __restrict__ mvx, int n) {
    __shared__ float As[32][132];
    __shared__ float Ws[32][128];
    float acc[8][8] = {};
    gemm_main<128, 256>(xt, mvx, g_h, g_mvh, g_Wzr, n, acc, As, Ws);

    const int tid = threadIdx.x;
    const int tx = tid % 16, ty = tid / 16;
    const int rowBase = blockIdx.x * 128;
    const bool isZ = (tx < 8);
    #pragma unroll
    for (int ii = 0; ii < 8; ii++) {
        int gr = rowBase + ty * 8 + ii;
        if (gr >= n) break;
        #pragma unroll
        for (int jj = 0; jj < 8; jj++) {
            int c = tx * 8 + jj;
            if (isZ) {
                float zv = sigmoidf_(acc[ii][jj] + g_bz[c]);
                g_z[(size_t)gr * 64 + c] = zv;
            } else {
                int cc = c - 64;
                float rv = sigmoidf_(acc[ii][jj] + g_br[cc]);
                g_hr[(size_t)gr * 64 + cc] = rv * g_h[(size_t)gr * 64 + cc];
            }
        }
    }
}

// h GEMM: A = [x_t | mvx | hr | mvhr], W = g_Wh (256x64)
// epilogue: htilde = tanh(.); h = z*h + (1-z)*htilde
__global__ __launch_bounds__(128)
void k_gemm_h(const float* __restrict__ xt, int n) {
    __shared__ float As[32][132];
    __shared__ float Ws[32][64];
    float acc[8][8] = {};
    gemm_main<64, 128>(xt, g_mvx, g_hr, g_mvhr, g_Wh, n, acc, As, Ws);

    const int tid = threadIdx.x;
    const int tx = tid % 8, ty = tid / 8;
    const int rowBase = blockIdx.x * 128;
    #pragma unroll
    for (int ii = 0; ii < 8; ii++) {
        int gr = rowBase + ty * 8 + ii;
        if (gr >= n) break;
        #pragma unroll
        for (int jj = 0; jj < 8; jj++) {
            int c = tx * 8 + jj;
            float ht = tanhf(acc[ii][jj] + g_bh[c]);
            float z  = g_z[(size_t)gr * 64 + c];
            float hv = g_h[(size_t)gr * 64 + c];
            g_h[(size_t)gr * 64 + c] = z * hv + (1.0f - z) * ht;
        }
    }
}

// ---------------- final linear: out = h @ Wlin + blin (Nx64 @ 64x16) ----------------
__global__ __launch_bounds__(256)
void k_out(const float* __restrict__ Wlin, const float* __restrict__ blin,
           float* __restrict__ out, int n) {
    __shared__ float Ws[64][16];
    __shared__ float Hs[16][64];
    int tid = threadIdx.x;
    int rowBase = blockIdx.x * 16;
    #pragma unroll
    for (int i = 0; i < 4; i++) {
        int idx = tid + i * 256;
        reinterpret_cast<float*>(Ws)[idx] = Wlin[idx];
    }
    {
        int r = tid >> 4, c4 = tid & 15;
        int gr = rowBase + r;
        float4 v = make_float4(0.f, 0.f, 0.f, 0.f);
        if (gr < n) v = *reinterpret_cast<const float4*>(g_h + (size_t)gr * 64 + c4 * 4);
        *reinterpret_cast<float4*>(&Hs[r][c4 * 4]) = v;
    }
    __syncthreads();
    int r = tid >> 4, c = tid & 15;
    float s = blin[c];
    #pragma unroll
    for (int k = 0; k < 64; k++) s += Hs[r][k] * Ws[k][c];
    int gr = rowBase + r;
    if (gr < n) out[(size_t)gr * 16 + c] = s;
}

// ---------------- host orchestration (graph-capturable) ----------------
extern "C" void kernel_launch(void* const* d_in, const int* in_sizes, int n_in,
                              void* d_out, int out_size) {
    const float* X  = (const float*)d_in[0];
    const void*  EI = d_in[1];
    const float* Wxz = (const float*)d_in[2];
    const float* bxz = (const float*)d_in[3];
    const float* Whz = (const float*)d_in[4];
    const float* bhz = (const float*)d_in[5];
    const float* Wxr = (const float*)d_in[6];
    const float* bxr = (const float*)d_in[7];
    const float* Whr = (const float*)d_in[8];
    const float* bhr = (const float*)d_in[9];
    const float* Wxh = (const float*)d_in[10];
    const float* bxh = (const float*)d_in[11];
    const float* Whh = (const float*)d_in[12];
    const float* bhh = (const float*)d_in[13];
    const float* Wlin = (const float*)d_in[14];
    const float* blin = (const float*)d_in[15];
    float* out = (float*)d_out;

    const int n = NN;
    const int E = in_sizes[1] / 2;      // element count of edge_index = 2*E

    float *p_h, *p_mvx, *p_mvh, *p_hr, *p_mvhr;
    cudaGetSymbolAddress((void**)&p_h,    g_h);
    cudaGetSymbolAddress((void**)&p_mvx,  g_mvx);
    cudaGetSymbolAddress((void**)&p_mvh,  g_mvh);
    cudaGetSymbolAddress((void**)&p_hr,   g_hr);
    cudaGetSymbolAddress((void**)&p_mvhr, g_mvhr);

    // graph setup: dtype detect, degrees, dinv, CSR
    k_detect<<<1, 32>>>((const int*)EI);
    k_zero_setup<<<(n + 255) / 256, 256>>>(n);
    k_zero_h<<<(NN * 64 + 255) / 256, 256>>>();
    k_hist<<<(E + 255) / 256, 256>>>(EI, E);
    k_dinv<<<(n + 255) / 256, 256>>>(n);
    int nb = (n + 1023) / 1024;
    k_scan1<<<nb, 1024>>>(n);
    k_scan2<<<1, 32>>>(nb);
    k_scan3<<<(n + 255) / 256, 256>>>(n, E);
    k_fill<<<(E + 255) / 256, 256>>>(EI, E);
    k_pack<<<(256 * 128 + 256 * 64 + 192 + 255) / 256, 256>>>(
        Wxz, Whz, Wxr, Whr, Wxh, Whh, bxz, bhz, bxr, bhr, bxh, bhh);

    dim3 sb(64, 4);
    int sgrid = (n + 3) / 4;
    int ggrid = (n + 127) / 128;

    for (int t = 0; t < TT; t++) {
        const float* xt = X + (size_t)t * n * 64;
        k_spmv<<<sgrid, sb>>>(xt, p_mvx, n);
        k_spmv<<<sgrid, sb>>>(p_h, p_mvh, n);
        k_gemm_zr<<<ggrid, 256>>>(xt, p_mvx, n);
        k_spmv<<<sgrid, sb>>>(p_hr, p_mvhr, n);
        k_gemm_h<<<ggrid, 128>>>(xt, n);
    }

    k_out<<<(n + 15) / 16, 256>>>(Wlin, blin, out, n);
}

// round 4
// speedup vs baseline: 1.8166x; 1.8166x over previous
#include <cuda_runtime.h>
#include <cuda_bf16.h>
#include <math.h>
#include <stdint.h>

#define NN 100000
#define EE 1250000
#define TT 8

// ---------------- device scratch (static, no allocation) ----------------
__device__ __align__(128) int   g_deg[NN];
__device__ __align__(128) int   g_cnt[NN];
__device__ __align__(128) int   g_cursor[NN];
__device__ __align__(128) int   g_rowptr[NN + 1];
__device__ __align__(128) int   g_bsum[256];
__device__ __align__(128) int   g_boff[256];
__device__ __align__(128) float g_dinv[NN];
__device__ __align__(128) int   g_col[EE];
__device__ __align__(128) float g_w[EE];
__device__ int g_is64;

__device__ __align__(128) float g_h[(size_t)NN * 64];
__device__ __align__(128) float g_mvx[(size_t)NN * 64];
__device__ __align__(128) float g_mvh[(size_t)NN * 64];
__device__ __align__(128) float g_hr[(size_t)NN * 64];
__device__ __align__(128) float g_mvhr[(size_t)NN * 64];
__device__ __align__(128) float g_z[(size_t)NN * 64];

// packed bf16 weights, linear layout: [chunk(4)][hi/lo(2)][k(64)][n(BN)]
__device__ __align__(128) __nv_bfloat16 g_Bzr[4 * 2 * 64 * 128];
__device__ __align__(128) __nv_bfloat16 g_Bh[4 * 2 * 64 * 64];

__device__ __align__(128) float g_bz[64];
__device__ __align__(128) float g_br[64];
__device__ __align__(128) float g_bh[64];

// ---------------- PTX helpers (sm_80-era, no arch-feature gating) ----------
__device__ __forceinline__ uint32_t smem_u32(const void* p) {
    uint32_t a;
    asm("{ .reg .u64 t; cvta.to.shared.u64 t, %1; cvt.u32.u64 %0, t; }" : "=r"(a) : "l"(p));
    return a;
}
__device__ __forceinline__ void ldm_x4(uint32_t* r, uint32_t a) {
    asm volatile("ldmatrix.sync.aligned.m8n8.x4.shared.b16 {%0,%1,%2,%3}, [%4];"
        : "=r"(r[0]), "=r"(r[1]), "=r"(r[2]), "=r"(r[3]) : "r"(a));
}
__device__ __forceinline__ void ldm_x2t(uint32_t& r0, uint32_t& r1, uint32_t a) {
    asm volatile("ldmatrix.sync.aligned.m8n8.x2.trans.shared.b16 {%0,%1}, [%2];"
        : "=r"(r0), "=r"(r1) : "r"(a));
}
__device__ __forceinline__ void mma16816(float* c, const uint32_t* a, uint32_t b0, uint32_t b1) {
    asm volatile("mma.sync.aligned.m16n8k16.row.col.f32.bf16.bf16.f32 "
        "{%0,%1,%2,%3}, {%4,%5,%6,%7}, {%8,%9}, {%0,%1,%2,%3};"
        : "+f"(c[0]), "+f"(c[1]), "+f"(c[2]), "+f"(c[3])
        : "r"(a[0]), "r"(a[1]), "r"(a[2]), "r"(a[3]), "r"(b0), "r"(b1));
}

// ---------------- dtype detection for edge_index (int32 vs int64) ----------
__global__ void k_detect(const int* __restrict__ ei) {
    if (blockIdx.x == 0 && threadIdx.x == 0) {
        int is64 = 1;
        for (int i = 0; i < 512; i++)
            if (ei[2 * i + 1] != 0) { is64 = 0; break; }
        g_is64 = is64;
    }
}
__device__ __forceinline__ int load_idx(const void* ei, size_t i) {
    if (g_is64) return (int)((const long long*)ei)[i];
    return ((const int*)ei)[i];
}

// ---------------- setup kernels ----------------
__global__ void k_zero_setup(int n) {
    int i = blockIdx.x * blockDim.x + threadIdx.x;
    if (i < n) { g_deg[i] = 0; g_cnt[i] = 0; g_cursor[i] = 0; }
}
__global__ void k_zero_h() {
    int i = blockIdx.x * blockDim.x + threadIdx.x;
    if (i < NN * 64) g_h[i] = 0.0f;
}
__global__ void k_hist(const void* __restrict__ ei, int E) {
    int e = blockIdx.x * blockDim.x + threadIdx.x;
    if (e < E) {
        int s = load_idx(ei, e);
        int d = load_idx(ei, (size_t)E + e);
        if (s >= 0 && s < NN) atomicAdd(&g_deg[s], 1);
        if (d >= 0 && d < NN) atomicAdd(&g_cnt[d], 1);
    }
}
__global__ void k_dinv(int n) {
    int i = blockIdx.x * blockDim.x + threadIdx.x;
    if (i < n) {
        int d = g_deg[i];
        g_dinv[i] = (d > 0) ? rsqrtf((float)d) : 0.0f;
    }
}
__global__ void k_scan1(int n) {
    __shared__ int s[1024];
    int tid = threadIdx.x;
    int gid = blockIdx.x * 1024 + tid;
    int v = (gid < n) ? g_cnt[gid] : 0;
    s[tid] = v;
    __syncthreads();
    #pragma unroll
    for (int off = 1; off < 1024; off <<= 1) {
        int t = (tid >= off) ? s[tid - off] : 0;
        __syncthreads();
        s[tid] += t;
        __syncthreads();
    }
    if (gid < n) g_rowptr[gid] = s[tid] - v;
    if (tid == 1023) g_bsum[blockIdx.x] = s[1023];
}
__global__ void k_scan2(int nb) {
    if (threadIdx.x == 0) {
        int acc = 0;
        for (int i = 0; i < nb; i++) { int t = g_bsum[i]; g_boff[i] = acc; acc += t; }
    }
}
__global__ void k_scan3(int n, int E) {
    int gid = blockIdx.x * blockDim.x + threadIdx.x;
    if (gid < n) g_rowptr[gid] += g_boff[gid >> 10];
    if (gid == 0) g_rowptr[n] = E;
}
__global__ void k_fill(const void* __restrict__ ei, int E) {
    int e = blockIdx.x * blockDim.x + threadIdx.x;
    if (e >= E) return;
    int s = load_idx(ei, e);
    int d = load_idx(ei, (size_t)E + e);
    if (s < 0 || s >= NN || d < 0 || d >= NN) return;
    int pos = g_rowptr[d] + atomicAdd(&g_cursor[d], 1);
    g_col[pos] = s;
    g_w[pos] = -g_dinv[s] * g_dinv[d];
}

// ---------------- weight packing: fp32 -> bf16 hi/lo, linear chunks --------
__global__ void k_pack_zr(const float* __restrict__ Wxz, const float* __restrict__ Whz,
                          const float* __restrict__ Wxr, const float* __restrict__ Whr) {
    int i = blockIdx.x * blockDim.x + threadIdx.x;
    if (i >= 256 * 128) return;
    int k = i >> 7, nout = i & 127;
    int kb = k >> 6, kr = k & 63;
    const float* W; int cc;
    if (nout < 64) { W = (kb < 2) ? Wxz : Whz; cc = nout; }
    else           { W = (kb < 2) ? Wxr : Whr; cc = nout - 64; }
    float v = W[(kb & 1) * 4096 + kr * 64 + cc];
    __nv_bfloat16 hb = __float2bfloat16(v);
    __nv_bfloat16 lb = __float2bfloat16(v - __bfloat162float(hb));
    int base = kb * 16384 + kr * 128 + nout;
    g_Bzr[base]        = hb;
    g_Bzr[base + 8192] = lb;
}
__global__ void k_pack_h(const float* __restrict__ Wxh, const float* __restrict__ Whh) {
    int i = blockIdx.x * blockDim.x + threadIdx.x;
    if (i >= 256 * 64) return;
    int k = i >> 6, nout = i & 63;
    int kb = k >> 6, kr = k & 63;
    const float* W = (kb < 2) ? Wxh : Whh;
    float v = W[(kb & 1) * 4096 + kr * 64 + nout];
    __nv_bfloat16 hb = __float2bfloat16(v);
    __nv_bfloat16 lb = __float2bfloat16(v - __bfloat162float(hb));
    int base = kb * 8192 + kr * 64 + nout;
    g_Bh[base]        = hb;
    g_Bh[base + 4096] = lb;
}
__global__ void k_pack_bias(const float* __restrict__ bxz, const float* __restrict__ bhz,
                            const float* __restrict__ bxr, const float* __restrict__ bhr,
                            const float* __restrict__ bxh, const float* __restrict__ bhh) {
    int c = threadIdx.x;
    if (c < 64) {
        g_bz[c] = bxz[c] + bhz[c];
        g_br[c] = bxr[c] + bhr[c];
        g_bh[c] = bxh[c] + bhh[c];
    }
}

// ---------------- spmv: y = L_tilde @ x (CSR by dst) ----------------
__global__ void k_spmv(const float* __restrict__ x, float* __restrict__ y, int n) {
    int row = blockIdx.x * 4 + threadIdx.y;
    if (row >= n) return;
    int f = threadIdx.x;
    int s = g_rowptr[row], e = g_rowptr[row + 1];
    float acc = 0.0f;
    for (int p = s; p < e; p++) {
        int c = g_col[p];
        float w = g_w[p];
        acc += w * x[(size_t)c * 64 + f];
    }
    y[(size_t)row * 64 + f] = acc;
}

// ---------------- mma.sync GEMM core ----------------
// C(128 x BN) = [A0|A1|A2|A3](128 x 256) @ W(256 x BN), bf16 3-split.
// Per chunk c (K=64, source c): A -> smem bf16 hi/lo (stride 72),
// W chunk copied to smem (stride BN+8). ldmatrix + mma.m16n8k16.
template <int BN, int MB>
__device__ __forceinline__ void mma_core(
    const float* __restrict__ A0, const float* __restrict__ A1,
    const float* __restrict__ A2, const float* __restrict__ A3,
    const __nv_bfloat16* __restrict__ Bpk, int n,
    int warpRow, int warpCol, float (&acc)[MB][8][4], char* sm)
{
    constexpr int ASTR = 72;                 // bf16 elements per A row
    constexpr int A_BYTES = 128 * ASTR * 2;  // 18432
    constexpr int WSTR = BN + 8;
    constexpr int W_BYTES = 64 * WSTR * 2;
    constexpr int W_OFF = 2 * A_BYTES;

    const int tid = threadIdx.x;
    const int lane = tid & 31;
    uint32_t s_ah = smem_u32(sm);
    uint32_t s_wh = s_ah + W_OFF;

    const float* srcs[4] = {A0, A1, A2, A3};
    const int r  = tid >> 1;
    const int kh = (tid & 1) * 32;
    const int gr = blockIdx.x * 128 + r;
    const bool ok = (gr < n);

    #pragma unroll 1
    for (int c = 0; c < 4; c++) {
        if (c) __syncthreads();

        // ---- A chunk: 128 x 64 fp32 -> bf16 hi/lo ----
        const float* src = srcs[c];
        #pragma unroll
        for (int i = 0; i < 8; i++) {
            float4 v = make_float4(0.f, 0.f, 0.f, 0.f);
            if (ok) v = *reinterpret_cast<const float4*>(src + (size_t)gr * 64 + kh + i * 4);
            __nv_bfloat16 hx = __float2bfloat16(v.x);
            __nv_bfloat16 hy = __float2bfloat16(v.y);
            __nv_bfloat16 hz = __float2bfloat16(v.z);
            __nv_bfloat16 hw = __float2bfloat16(v.w);
            __nv_bfloat16 lx = __float2bfloat16(v.x - __bfloat162float(hx));
            __nv_bfloat16 ly = __float2bfloat16(v.y - __bfloat162float(hy));
            __nv_bfloat16 lz = __float2bfloat16(v.z - __bfloat162float(hz));
            __nv_bfloat16 lw = __float2bfloat16(v.w - __bfloat162float(hw));
            uint2 hv2 = make_uint2(
                (uint32_t)__bfloat16_as_ushort(hx) | ((uint32_t)__bfloat16_as_ushort(hy) << 16),
                (uint32_t)__bfloat16_as_ushort(hz) | ((uint32_t)__bfloat16_as_ushort(hw) << 16));
            uint2 lv2 = make_uint2(
                (uint32_t)__bfloat16_as_ushort(lx) | ((uint32_t)__bfloat16_as_ushort(ly) << 16),
                (uint32_t)__bfloat16_as_ushort(lz) | ((uint32_t)__bfloat16_as_ushort(lw) << 16));
            uint32_t off = (uint32_t)(r * ASTR + kh + i * 4) * 2;
            *reinterpret_cast<uint2*>(sm + off)           = hv2;
            *reinterpret_cast<uint2*>(sm + A_BYTES + off) = lv2;
        }

        // ---- W chunk: linear global -> padded smem ----
        {
            const uint4* bs = reinterpret_cast<const uint4*>(Bpk + (size_t)c * 2 * 64 * BN);
            constexpr int ROWU4 = BN / 8;          // uint4 per row
            constexpr int TOT = 64 * ROWU4;        // per component
            #pragma unroll
            for (int sel = 0; sel < 2; sel++) {
                char* wd = sm + W_OFF + sel * W_BYTES;
                #pragma unroll
                for (int it = 0; it < TOT / 256; it++) {
                    int u = tid + it * 256;
                    int k = u / ROWU4, q = u % ROWU4;
                    *reinterpret_cast<uint4*>(wd + k * WSTR * 2 + q * 16) = bs[sel * TOT + u];
                }
            }
        }
        __syncthreads();

        // ---- compute: 4 ksteps of 16 ----
        #pragma unroll
        for (int ks = 0; ks < 4; ks++) {
            const int k0 = ks * 16;
            uint32_t ah[MB][4], al[MB][4];
            #pragma unroll
            for (int mb = 0; mb < MB; mb++) {
                int rowoff = warpRow + mb * 16 + ((lane >> 3) & 1) * 8 + (lane & 7);
                int coloff = k0 + (lane >> 4) * 8;
                uint32_t ad = s_ah + (uint32_t)(rowoff * ASTR + coloff) * 2;
                ldm_x4(ah[mb], ad);
                ldm_x4(al[mb], ad + A_BYTES);
            }
            #pragma unroll
            for (int nb = 0; nb < 8; nb++) {
                int n0 = warpCol + nb * 8;
                int kk = k0 + (lane & 15);
                uint32_t bd = s_wh + (uint32_t)(kk * WSTR + n0) * 2;
                uint32_t bh0, bh1, bl0, bl1;
                ldm_x2t(bh0, bh1, bd);
                ldm_x2t(bl0, bl1, bd + W_BYTES);
                #pragma unroll
                for (int mb = 0; mb < MB; mb++) {
                    mma16816(acc[mb][nb], ah[mb], bh0, bh1);
                    mma16816(acc[mb][nb], al[mb], bh0, bh1);
                    mma16816(acc[mb][nb], ah[mb], bl0, bl1);
                }
            }
        }
    }
}

__device__ __forceinline__ float sigmoidf_(float x) { return 1.0f / (1.0f + expf(-x)); }

// z/r GEMM: A = [x_t | mvx | h | mvh], W = g_Bzr (256x128)
__global__ __launch_bounds__(256, 1)
void k_gemm_zr_mma(const float* __restrict__ xt, const float* __restrict__ mvx, int n) {
    extern __shared__ char sm[];
    const int w = threadIdx.x >> 5, lane = threadIdx.x & 31;
    const int warpRow = (w & 3) * 32;
    const int warpCol = (w >> 2) * 64;
    float acc[2][8][4] = {};
    mma_core<128, 2>(xt, mvx, g_h, g_mvh, g_Bzr, n, warpRow, warpCol, acc, sm);

    const bool isZ = (warpCol == 0);
    const int rbase = blockIdx.x * 128 + warpRow;
    #pragma unroll
    for (int mb = 0; mb < 2; mb++) {
        #pragma unroll
        for (int h2 = 0; h2 < 2; h2++) {
            int row = rbase + mb * 16 + (lane >> 2) + h2 * 8;
            if (row >= n) continue;
            #pragma unroll
            for (int nb = 0; nb < 8; nb++) {
                int cc = nb * 8 + (lane & 3) * 2;
                float v0 = acc[mb][nb][h2 * 2 + 0];
                float v1 = acc[mb][nb][h2 * 2 + 1];
                if (isZ) {
                    float2 o;
                    o.x = sigmoidf_(v0 + g_bz[cc]);
                    o.y = sigmoidf_(v1 + g_bz[cc + 1]);
                    *reinterpret_cast<float2*>(&g_z[(size_t)row * 64 + cc]) = o;
                } else {
                    float2 hv = *reinterpret_cast<const float2*>(&g_h[(size_t)row * 64 + cc]);
                    float2 o;
                    o.x = sigmoidf_(v0 + g_br[cc])     * hv.x;
                    o.y = sigmoidf_(v1 + g_br[cc + 1]) * hv.y;
                    *reinterpret_cast<float2*>(&g_hr[(size_t)row * 64 + cc]) = o;
                }
            }
        }
    }
}

// h GEMM: A = [x_t | mvx | hr | mvhr], W = g_Bh (256x64); GRU update epilogue
__global__ __launch_bounds__(256, 1)
void k_gemm_h_mma(const float* __restrict__ xt, int n) {
    extern __shared__ char sm[];
    const int w = threadIdx.x >> 5, lane = threadIdx.x & 31;
    float acc[1][8][4] = {};
    mma_core<64, 1>(xt, g_mvx, g_hr, g_mvhr, g_Bh, n, w * 16, 0, acc, sm);

    const int rbase = blockIdx.x * 128 + w * 16;
    #pragma unroll
    for (int h2 = 0; h2 < 2; h2++) {
        int row = rbase + (lane >> 2) + h2 * 8;
        if (row >= n) continue;
        #pragma unroll
        for (int nb = 0; nb < 8; nb++) {
            int cc = nb * 8 + (lane & 3) * 2;
            float t0 = tanhf(acc[0][nb][h2 * 2 + 0] + g_bh[cc]);
            float t1 = tanhf(acc[0][nb][h2 * 2 + 1] + g_bh[cc + 1]);
            float2 zv = *reinterpret_cast<const float2*>(&g_z[(size_t)row * 64 + cc]);
            float2 hv = *reinterpret_cast<const float2*>(&g_h[(size_t)row * 64 + cc]);
            float2 o;
            o.x = zv.x * hv.x + (1.0f - zv.x) * t0;
            o.y = zv.y * hv.y + (1.0f - zv.y) * t1;
            *reinterpret_cast<float2*>(&g_h[(size_t)row * 64 + cc]) = o;
        }
    }
}

// ---------------- final linear: out = h @ Wlin + blin (Nx64 @ 64x16) --------
__global__ __launch_bounds__(256)
void k_out(const float* __restrict__ Wlin, const float* __restrict__ blin,
           float* __restrict__ out, int n) {
    __shared__ float Ws[64][16];
    __shared__ float Hs[16][64];
    int tid = threadIdx.x;
    int rowBase = blockIdx.x * 16;
    #pragma unroll
    for (int i = 0; i < 4; i++) {
        int idx = tid + i * 256;
        reinterpret_cast<float*>(Ws)[idx] = Wlin[idx];
    }
    {
        int r = tid >> 4, c4 = tid & 15;
        int gr = rowBase + r;
        float4 v = make_float4(0.f, 0.f, 0.f, 0.f);
        if (gr < n) v = *reinterpret_cast<const float4*>(g_h + (size_t)gr * 64 + c4 * 4);
        *reinterpret_cast<float4*>(&Hs[r][c4 * 4]) = v;
    }
    __syncthreads();
    int r = tid >> 4, c = tid & 15;
    float s = blin[c];
    #pragma unroll
    for (int k = 0; k < 64; k++) s += Hs[r][k] * Ws[k][c];
    int gr = rowBase + r;
    if (gr < n) out[(size_t)gr * 16 + c] = s;
}

// ---------------- host orchestration (graph-capturable) ----------------
extern "C" void kernel_launch(void* const* d_in, const int* in_sizes, int n_in,
                              void* d_out, int out_size) {
    const float* X  = (const float*)d_in[0];
    const void*  EI = d_in[1];
    const float* Wxz = (const float*)d_in[2];
    const float* bxz = (const float*)d_in[3];
    const float* Whz = (const float*)d_in[4];
    const float* bhz = (const float*)d_in[5];
    const float* Wxr = (const float*)d_in[6];
    const float* bxr = (const float*)d_in[7];
    const float* Whr = (const float*)d_in[8];
    const float* bhr = (const float*)d_in[9];
    const float* Wxh = (const float*)d_in[10];
    const float* bxh = (const float*)d_in[11];
    const float* Whh = (const float*)d_in[12];
    const float* bhh = (const float*)d_in[13];
    const float* Wlin = (const float*)d_in[14];
    const float* blin = (const float*)d_in[15];
    float* out = (float*)d_out;

    const int n = NN;
    const int E = in_sizes[1] / 2;

    float *p_h, *p_mvx, *p_mvh, *p_hr, *p_mvhr;
    cudaGetSymbolAddress((void**)&p_h,    g_h);
    cudaGetSymbolAddress((void**)&p_mvx,  g_mvx);
    cudaGetSymbolAddress((void**)&p_mvh,  g_mvh);
    cudaGetSymbolAddress((void**)&p_hr,   g_hr);
    cudaGetSymbolAddress((void**)&p_mvhr, g_mvhr);

    // dynamic SMEM: A hi/lo (2*18432) + W hi/lo padded
    const int SMEM_ZR = 2 * 18432 + 2 * 64 * (128 + 8) * 2;   // 71680
    const int SMEM_H  = 2 * 18432 + 2 * 64 * (64 + 8) * 2;    // 55296
    cudaFuncSetAttribute(k_gemm_zr_mma, cudaFuncAttributeMaxDynamicSharedMemorySize, SMEM_ZR);
    cudaFuncSetAttribute(k_gemm_h_mma,  cudaFuncAttributeMaxDynamicSharedMemorySize, SMEM_H);

    // graph setup: dtype detect, degrees, dinv, CSR, weight packing
    k_detect<<<1, 32>>>((const int*)EI);
    k_zero_setup<<<(n + 255) / 256, 256>>>(n);
    k_zero_h<<<(NN * 64 + 255) / 256, 256>>>();
    k_hist<<<(E + 255) / 256, 256>>>(EI, E);
    k_dinv<<<(n + 255) / 256, 256>>>(n);
    int nb = (n + 1023) / 1024;
    k_scan1<<<nb, 1024>>>(n);
    k_scan2<<<1, 32>>>(nb);
    k_scan3<<<(n + 255) / 256, 256>>>(n, E);
    k_fill<<<(E + 255) / 256, 256>>>(EI, E);
    k_pack_zr<<<(256 * 128 + 255) / 256, 256>>>(Wxz, Whz, Wxr, Whr);
    k_pack_h<<<(256 * 64 + 255) / 256, 256>>>(Wxh, Whh);
    k_pack_bias<<<1, 64>>>(bxz, bhz, bxr, bhr, bxh, bhh);

    dim3 sb(64, 4);
    int sgrid = (n + 3) / 4;
    int ggrid = (n + 127) / 128;

    for (int t = 0; t < TT; t++) {
        const float* xt = X + (size_t)t * n * 64;
        k_spmv<<<sgrid, sb>>>(xt, p_mvx, n);
        k_spmv<<<sgrid, sb>>>(p_h, p_mvh, n);
        k_gemm_zr_mma<<<ggrid, 256, SMEM_ZR>>>(xt, p_mvx, n);
        k_spmv<<<sgrid, sb>>>(p_hr, p_mvhr, n);
        k_gemm_h_mma<<<ggrid, 256, SMEM_H>>>(xt, n);
    }

    k_out<<<(n + 15) / 16, 256>>>(Wlin, blin, out, n);
}